// round 10
// baseline (speedup 1.0000x reference)
#include <cuda_runtime.h>
#include <cuda_fp16.h>
#include <math.h>
#include <stdint.h>

#define NLV   16
#define TBITS 19
#define TSZ   (1u << TBITS)
#define BLOCK 256
#define PD_CAP 393216   // capacity of dense pair-table (entries), actual 330940

typedef unsigned int u32;

struct LvlParams {
    float scale[NLV];
    int   res[NLV];
    int   dense[NLV];
    int   pdoff[NLV];
};

struct BuildParams {
    int lvl[8];
    int res[8];
    int off[8];
    int nd;
    int total;
};

// dense pair-table: entry pdoff[l]+j holds (T[j], T[j+1 along x, clamped])
__device__ __align__(16) float4 g_pd[PD_CAP];

// softplus(10z)/10 = max(z,0) + (ln2/10)*lg2(1 + 2^(-10*log2e*|z|))
__device__ __forceinline__ float softplus10(float z) {
    float e, l;
    float a = -14.426950408889634f * fabsf(z);
    asm("ex2.approx.ftz.f32 %0, %1;" : "=f"(e) : "f"(a));
    float p = 1.0f + e;
    asm("lg2.approx.ftz.f32 %0, %1;" : "=f"(l) : "f"(p));
    return fmaf(l, 0.069314718055994531f, fmaxf(z, 0.0f));
}

__device__ __forceinline__ u32 f22h2(float hi, float lo) {
    u32 r;
    asm("cvt.rn.f16x2.f32 %0, %1, %2;" : "=r"(r) : "f"(hi), "f"(lo));
    return r;
}

__device__ __forceinline__ void ldsm4(u32& r0, u32& r1, u32& r2, u32& r3, u32 addr) {
    asm volatile("ldmatrix.sync.aligned.m8n8.x4.shared.b16 {%0,%1,%2,%3}, [%4];"
        : "=r"(r0), "=r"(r1), "=r"(r2), "=r"(r3) : "r"(addr));
}

__device__ __forceinline__ void mma16816(float* d, const u32* a, u32 b0, u32 b1) {
    asm volatile("mma.sync.aligned.m16n8k16.row.col.f32.f16.f16.f32 "
        "{%0,%1,%2,%3},{%4,%5,%6,%7},{%8,%9},{%0,%1,%2,%3};"
        : "+f"(d[0]), "+f"(d[1]), "+f"(d[2]), "+f"(d[3])
        : "r"(a[0]), "r"(a[1]), "r"(a[2]), "r"(a[3]), "r"(b0), "r"(b1));
}

// =============== build kernel: dense pair-table ===============
__global__ void build_pd(const float* __restrict__ table, BuildParams B)
{
    int f = blockIdx.x * blockDim.x + threadIdx.x;
    if (f >= B.total) return;
    int l = 0, res = 1, j = f;
    #pragma unroll
    for (int d = 0; d < 8; d++) {
        if (d < B.nd && f >= B.off[d]) { l = B.lvl[d]; res = B.res[d]; j = f - B.off[d]; }
    }
    const float2* t2 = reinterpret_cast<const float2*>(table) + (size_t)l * TSZ;
    int qx = j % res;
    float2 c0 = __ldg(&t2[j]);
    float2 c1 = __ldg(&t2[(qx < res - 1) ? j + 1 : j]);
    g_pd[f] = make_float4(c0.x, c0.y, c1.x, c1.y);
}

// index setup for one level.
// dense: idx[p] = g_pd entry; no fallback.
// hashed: idx[p] = i0 (float2 index), i1[p] = x+1 neighbor index.
__device__ __forceinline__ void lvl_setup(float px, float py, float pz,
                                          float sc, int res, bool dens, int pdoff,
                                          u32 idx[4], u32 i1[4], float w[3])
{
    float fx = px * sc + 0.5f, fy = py * sc + 0.5f, fz = pz * sc + 0.5f;
    float gx = floorf(fx), gy = floorf(fy), gz = floorf(fz);
    w[0] = fx - gx; w[1] = fy - gy; w[2] = fz - gz;
    int cx = (int)gx, cy = (int)gy, cz = (int)gz;

    if (dens) {
        int jx  = min(max(cx, 0), res - 1);
        int ty0 = min(max(cy,     0), res - 1) * res;
        int ty1 = min(max(cy + 1, 0), res - 1) * res;
        int tz0 = min(max(cz,     0), res - 1) * (res * res);
        int tz1 = min(max(cz + 1, 0), res - 1) * (res * res);
        int base = pdoff + jx;
        idx[0] = (u32)(base + ty0 + tz0);
        idx[1] = (u32)(base + ty0 + tz1);
        idx[2] = (u32)(base + ty1 + tz0);
        idx[3] = (u32)(base + ty1 + tz1);
    } else {
        u32 ux = (u32)cx, uy = (u32)cy, uz = (u32)cz;
        u32 ty0 = uy * 2654435761u, ty1 = ty0 + 2654435761u;
        u32 tz0 = uz * 805459861u,  tz1 = tz0 + 805459861u;
        #pragma unroll
        for (int p = 0; p < 4; p++) {
            u32 s = (((p >> 1) & 1) ? ty1 : ty0) ^ ((p & 1) ? tz1 : tz0);
            idx[p] = (ux ^ s) & (TSZ - 1u);
            i1[p]  = ((ux + 1u) ^ s) & (TSZ - 1u);
        }
    }
}

// dense reduce: q[p] = (c0.x, c0.y, c1.x, c1.y)
__device__ __forceinline__ u32 reduce_dense(const float4 q[4], const float w[3]) {
    const float wx = w[0], wy = w[1], wz = w[2];
    const float wx0 = 1.f - wx, wy0 = 1.f - wy, wz0 = 1.f - wz;
    float f0 = 0.f, f1 = 0.f;
    #pragma unroll
    for (int p = 0; p < 4; p++) {
        const int oy = (p >> 1) & 1, oz = p & 1;
        float wyz = (oy ? wy : wy0) * (oz ? wz : wz0);
        float w0 = wx0 * wyz, w1 = wx * wyz;
        f0 = fmaf(w0, q[p].x, fmaf(w1, q[p].z, f0));
        f1 = fmaf(w0, q[p].y, fmaf(w1, q[p].w, f1));
    }
    return f22h2(f1, f0);
}

// hashed reduce with parity select + fallback
__device__ __forceinline__ u32 reduce_hash(const float4 q[4], const float2 e[4],
                                           const u32 i0[4], const u32 i1[4],
                                           const float w[3])
{
    const float wx = w[0], wy = w[1], wz = w[2];
    const float wx0 = 1.f - wx, wy0 = 1.f - wy, wz0 = 1.f - wz;
    float f0 = 0.f, f1 = 0.f;
    #pragma unroll
    for (int p = 0; p < 4; p++) {
        const int oy = (p >> 1) & 1, oz = p & 1;
        const bool hi = (i0[p] & 1u) != 0u;
        float2 c0 = hi ? make_float2(q[p].z, q[p].w) : make_float2(q[p].x, q[p].y);
        float2 ot = hi ? make_float2(q[p].x, q[p].y) : make_float2(q[p].z, q[p].w);
        float2 c1 = ((i0[p] ^ i1[p]) == 1u) ? ot : e[p];
        float wyz = (oy ? wy : wy0) * (oz ? wz : wz0);
        float w0 = wx0 * wyz, w1 = wx * wyz;
        f0 = fmaf(w0, c0.x, fmaf(w1, c1.x, f0));
        f1 = fmaf(w0, c0.y, fmaf(w1, c1.y, f1));
    }
    return f22h2(f1, f0);
}

__global__ void __launch_bounds__(BLOCK, 3)
sdf_kernel(const float* __restrict__ x,
           const float* __restrict__ table,
           const float* __restrict__ w1,
           const float* __restrict__ w2,
           const float* __restrict__ w3,
           const float* __restrict__ w4,
           float* __restrict__ out,
           int n, LvlParams P)
{
    __shared__ __align__(16) __half s_w1[64 * 40];
    __shared__ __align__(16) __half s_w2[64 * 72];
    __shared__ __align__(16) __half s_w3[64 * 72];
    __shared__ float s_w4[64];
    __shared__ __align__(16) __half s_enc[BLOCK * 40]; // row stride 40 halves (80B)

    const int tid  = threadIdx.x;
    const int lane = tid & 31;
    const int warp = tid >> 5;

    // ---- prologue: weights -> fp16 smem ----
    for (int t = tid; t < 64 * 32; t += BLOCK) {
        int nn = t >> 5, kk = t & 31;
        s_w1[nn * 40 + kk] = __float2half_rn(w1[t]);
    }
    for (int t = tid; t < 64 * 64; t += BLOCK) {
        int nn = t >> 6, kk = t & 63;
        s_w2[nn * 72 + kk] = __float2half_rn(w2[t]);
        s_w3[nn * 72 + kk] = __float2half_rn(w3[t]);
    }
    if (tid < 64) s_w4[tid] = w4[tid];
    __syncthreads();

    // ---- encode: level pairs, batched loads; pd table for dense levels ----
    const int i  = blockIdx.x * BLOCK + tid;
    const int ic = (i < n) ? i : (n - 1);
    const float px = x[3 * ic + 0];
    const float py = x[3 * ic + 1];
    const float pz = x[3 * ic + 2];

    u32* encw = reinterpret_cast<u32*>(s_enc);

    #pragma unroll 1
    for (int lp = 0; lp < NLV / 2; lp++) {
        const int lA = 2 * lp, lB = 2 * lp + 1;
        const bool dA = P.dense[lA] != 0, dB = P.dense[lB] != 0;
        u32 iA[4], jA[4], iB[4], jB[4];
        float wA[3], wB[3];
        lvl_setup(px, py, pz, P.scale[lA], P.res[lA], dA, P.pdoff[lA], iA, jA, wA);
        lvl_setup(px, py, pz, P.scale[lB], P.res[lB], dB, P.pdoff[lB], iB, jB, wB);

        const float2* tA = reinterpret_cast<const float2*>(table) + (size_t)lA * TSZ;
        const float2* tB = reinterpret_cast<const float2*>(table) + (size_t)lB * TSZ;
        const float4* t4A = reinterpret_cast<const float4*>(tA);
        const float4* t4B = reinterpret_cast<const float4*>(tB);

        // primary loads (batched: up to 8 LDG.128 in flight)
        float4 qA[4], qB[4];
        #pragma unroll
        for (int p = 0; p < 4; p++)
            qA[p] = dA ? __ldg(&g_pd[iA[p]]) : __ldg(&t4A[iA[p] >> 1]);
        #pragma unroll
        for (int p = 0; p < 4; p++)
            qB[p] = dB ? __ldg(&g_pd[iB[p]]) : __ldg(&t4B[iB[p] >> 1]);

        // fallback loads: hashed levels only, unmerged lanes only
        float2 eA[4], eB[4];
        if (!dA) {
            #pragma unroll
            for (int p = 0; p < 4; p++) {
                eA[p] = make_float2(0.f, 0.f);
                if ((iA[p] ^ jA[p]) != 1u) eA[p] = __ldg(&tA[jA[p]]);
            }
        }
        if (!dB) {
            #pragma unroll
            for (int p = 0; p < 4; p++) {
                eB[p] = make_float2(0.f, 0.f);
                if ((iB[p] ^ jB[p]) != 1u) eB[p] = __ldg(&tB[jB[p]]);
            }
        }

        encw[tid * 20 + lA] = dA ? reduce_dense(qA, wA) : reduce_hash(qA, eA, iA, jA, wA);
        encw[tid * 20 + lB] = dB ? reduce_dense(qB, wB) : reduce_hash(qB, eB, iB, jB, wB);
    }
    __syncwarp();  // enc rows are warp-private

    // ---- MLP on tensor cores: 32 pts/warp, sequential m-tiles (r8-verbatim) ----
    const u32 enc_b = (u32)__cvta_generic_to_shared(s_enc);
    const u32 w1_b  = (u32)__cvta_generic_to_shared(s_w1);
    const u32 w2_b  = (u32)__cvta_generic_to_shared(s_w2);
    const u32 w3_b  = (u32)__cvta_generic_to_shared(s_w3);

    #pragma unroll 1
    for (int mt = 0; mt < 2; mt++) {
        float d[8][4];
        u32   a[4][4];

        // layer 1: 32 -> 64
        #pragma unroll
        for (int kt = 0; kt < 2; kt++) {
            u32 addr = enc_b + (u32)((warp * 32 + mt * 16 + (lane & 15)) * 80
                                     + kt * 32 + (lane >> 4) * 16);
            ldsm4(a[kt][0], a[kt][1], a[kt][2], a[kt][3], addr);
        }
        #pragma unroll
        for (int nt = 0; nt < 8; nt++)
            #pragma unroll
            for (int v = 0; v < 4; v++) d[nt][v] = 0.f;

        #pragma unroll
        for (int kt = 0; kt < 2; kt++)
            #pragma unroll
            for (int u = 0; u < 4; u++) {
                u32 b0, b1, b2, b3;
                u32 addr = w1_b + (u32)((u * 16 + (lane >> 4) * 8 + (lane & 7)) * 80
                                        + kt * 32 + ((lane >> 3) & 1) * 16);
                ldsm4(b0, b1, b2, b3, addr);
                mma16816(d[2 * u],     a[kt], b0, b1);
                mma16816(d[2 * u + 1], a[kt], b2, b3);
            }

        #pragma unroll
        for (int kk = 0; kk < 4; kk++) {
            a[kk][0] = f22h2(softplus10(d[2*kk][1]),   softplus10(d[2*kk][0]));
            a[kk][1] = f22h2(softplus10(d[2*kk][3]),   softplus10(d[2*kk][2]));
            a[kk][2] = f22h2(softplus10(d[2*kk+1][1]), softplus10(d[2*kk+1][0]));
            a[kk][3] = f22h2(softplus10(d[2*kk+1][3]), softplus10(d[2*kk+1][2]));
        }

        // layers 2 and 3: 64 -> 64
        #pragma unroll 1
        for (int layer = 0; layer < 2; layer++) {
            const u32 wb = (layer == 0) ? w2_b : w3_b;
            #pragma unroll
            for (int nt = 0; nt < 8; nt++)
                #pragma unroll
                for (int v = 0; v < 4; v++) d[nt][v] = 0.f;

            #pragma unroll
            for (int kt = 0; kt < 4; kt++)
                #pragma unroll
                for (int u = 0; u < 4; u++) {
                    u32 b0, b1, b2, b3;
                    u32 addr = wb + (u32)((u * 16 + (lane >> 4) * 8 + (lane & 7)) * 144
                                          + kt * 32 + ((lane >> 3) & 1) * 16);
                    ldsm4(b0, b1, b2, b3, addr);
                    mma16816(d[2 * u],     a[kt], b0, b1);
                    mma16816(d[2 * u + 1], a[kt], b2, b3);
                }

            if (layer == 0) {
                #pragma unroll
                for (int kk = 0; kk < 4; kk++) {
                    a[kk][0] = f22h2(softplus10(d[2*kk][1]),   softplus10(d[2*kk][0]));
                    a[kk][1] = f22h2(softplus10(d[2*kk][3]),   softplus10(d[2*kk][2]));
                    a[kk][2] = f22h2(softplus10(d[2*kk+1][1]), softplus10(d[2*kk+1][0]));
                    a[kk][3] = f22h2(softplus10(d[2*kk+1][3]), softplus10(d[2*kk+1][2]));
                }
            }
        }

        // layer 4: 64 -> 1
        {
            float p0 = 0.f, p1 = 0.f;
            #pragma unroll
            for (int nt = 0; nt < 8; nt++) {
                int c = nt * 8 + 2 * (lane & 3);
                float wv0 = s_w4[c], wv1 = s_w4[c + 1];
                p0 = fmaf(softplus10(d[nt][0]), wv0, p0);
                p0 = fmaf(softplus10(d[nt][1]), wv1, p0);
                p1 = fmaf(softplus10(d[nt][2]), wv0, p1);
                p1 = fmaf(softplus10(d[nt][3]), wv1, p1);
            }
            p0 += __shfl_xor_sync(0xffffffffu, p0, 1);
            p0 += __shfl_xor_sync(0xffffffffu, p0, 2);
            p1 += __shfl_xor_sync(0xffffffffu, p1, 1);
            p1 += __shfl_xor_sync(0xffffffffu, p1, 2);
            if ((lane & 3) == 0) {
                int r0 = blockIdx.x * BLOCK + warp * 32 + mt * 16 + (lane >> 2);
                if (r0 < n) out[r0] = p0;
                int r1 = r0 + 8;
                if (r1 < n) out[r1] = p1;
            }
        }
    }
}

extern "C" void kernel_launch(void* const* d_in, const int* in_sizes, int n_in,
                              void* d_out, int out_size)
{
    const float* x     = (const float*)d_in[0];
    const float* table = (const float*)d_in[1];
    const float* w1    = (const float*)d_in[2];
    const float* w2    = (const float*)d_in[3];
    const float* w3    = (const float*)d_in[4];
    const float* w4    = (const float*)d_in[5];
    float* out = (float*)d_out;

    const int n = in_sizes[0] / 3;

    LvlParams P;
    BuildParams B;
    B.nd = 0; B.total = 0;
    const double pls = exp2(7.0 / 15.0);
    const double l2s = log2(pls);
    for (int l = 0; l < NLV; l++) {
        double s = exp2((double)l * l2s) * 16.0 - 1.0;
        P.scale[l] = (float)s;
        long long r = (long long)ceil(s) + 1;
        P.res[l] = (int)r;
        bool dn = (r * r * r <= (long long)TSZ);
        P.pdoff[l] = 0;
        P.dense[l] = 0;
        if (dn && B.nd < 8) {
            long long cnt = r * r * r;
            if (B.total + cnt <= PD_CAP) {
                P.dense[l] = 1;
                P.pdoff[l] = B.total;
                B.lvl[B.nd] = l;
                B.res[B.nd] = (int)r;
                B.off[B.nd] = B.total;
                B.nd++;
                B.total += (int)cnt;
            }
            // else: treated as hashed — impossible for these params, and the
            // hashed path would be wrong for a dense level; params are static.
        }
    }

    if (B.total > 0) {
        int bgrid = (B.total + 255) / 256;
        build_pd<<<bgrid, 256>>>(table, B);
    }

    int grid = (n + BLOCK - 1) / BLOCK;
    sdf_kernel<<<grid, BLOCK>>>(x, table, w1, w2, w3, w4, out, n, P);
}

// round 11
// speedup vs baseline: 1.5419x; 1.5419x over previous
#include <cuda_runtime.h>
#include <cuda_fp16.h>
#include <math.h>
#include <stdint.h>

#define NLV   16
#define TBITS 19
#define TSZ   (1u << TBITS)
#define BLOCK 256
#define PD_CAP 393216   // capacity of dense pair-table (entries), actual 330940

typedef unsigned int u32;

struct LvlParams {
    float scale[NLV];
    int   res[NLV];
    int   dense[NLV];
    int   pdoff[NLV];
};

struct BuildParams {
    int lvl[8];
    int res[8];
    int off[8];
    int nd;
    int total;
};

// dense pair-table: entry pdoff[l]+j holds (T[j], T[j+1 along x, clamped])
__device__ __align__(16) float4 g_pd[PD_CAP];

// softplus(10z)/10 = max(z,0) + (ln2/10)*lg2(1 + 2^(-10*log2e*|z|))
__device__ __forceinline__ float softplus10(float z) {
    float e, l;
    float a = -14.426950408889634f * fabsf(z);
    asm("ex2.approx.ftz.f32 %0, %1;" : "=f"(e) : "f"(a));
    float p = 1.0f + e;
    asm("lg2.approx.ftz.f32 %0, %1;" : "=f"(l) : "f"(p));
    return fmaf(l, 0.069314718055994531f, fmaxf(z, 0.0f));
}

__device__ __forceinline__ u32 f22h2(float hi, float lo) {
    u32 r;
    asm("cvt.rn.f16x2.f32 %0, %1, %2;" : "=r"(r) : "f"(hi), "f"(lo));
    return r;
}

__device__ __forceinline__ void ldsm4(u32& r0, u32& r1, u32& r2, u32& r3, u32 addr) {
    asm volatile("ldmatrix.sync.aligned.m8n8.x4.shared.b16 {%0,%1,%2,%3}, [%4];"
        : "=r"(r0), "=r"(r1), "=r"(r2), "=r"(r3) : "r"(addr));
}

__device__ __forceinline__ void mma16816(float* d, const u32* a, u32 b0, u32 b1) {
    asm volatile("mma.sync.aligned.m16n8k16.row.col.f32.f16.f16.f32 "
        "{%0,%1,%2,%3},{%4,%5,%6,%7},{%8,%9},{%0,%1,%2,%3};"
        : "+f"(d[0]), "+f"(d[1]), "+f"(d[2]), "+f"(d[3])
        : "r"(a[0]), "r"(a[1]), "r"(a[2]), "r"(a[3]), "r"(b0), "r"(b1));
}

// =============== build kernel: dense pair-table ===============
__global__ void build_pd(const float* __restrict__ table, BuildParams B)
{
    int f = blockIdx.x * blockDim.x + threadIdx.x;
    if (f >= B.total) return;
    int l = 0, res = 1, j = f;
    #pragma unroll
    for (int d = 0; d < 8; d++) {
        if (d < B.nd && f >= B.off[d]) { l = B.lvl[d]; res = B.res[d]; j = f - B.off[d]; }
    }
    const float2* t2 = reinterpret_cast<const float2*>(table) + (size_t)l * TSZ;
    int qx = j % res;
    float2 c0 = __ldg(&t2[j]);
    float2 c1 = __ldg(&t2[(qx < res - 1) ? j + 1 : j]);
    g_pd[f] = make_float4(c0.x, c0.y, c1.x, c1.y);
}

// index setup for one level.
// dense: idx[p] = g_pd entry; no fallback.
// hashed: idx[p] = i0 (float2 index), i1[p] = x+1 neighbor index.
__device__ __forceinline__ void lvl_setup(float px, float py, float pz,
                                          float sc, int res, bool dens, int pdoff,
                                          u32 idx[4], u32 i1[4], float w[3])
{
    float fx = px * sc + 0.5f, fy = py * sc + 0.5f, fz = pz * sc + 0.5f;
    float gx = floorf(fx), gy = floorf(fy), gz = floorf(fz);
    w[0] = fx - gx; w[1] = fy - gy; w[2] = fz - gz;
    int cx = (int)gx, cy = (int)gy, cz = (int)gz;

    if (dens) {
        int jx  = min(max(cx, 0), res - 1);
        int ty0 = min(max(cy,     0), res - 1) * res;
        int ty1 = min(max(cy + 1, 0), res - 1) * res;
        int tz0 = min(max(cz,     0), res - 1) * (res * res);
        int tz1 = min(max(cz + 1, 0), res - 1) * (res * res);
        int base = pdoff + jx;
        idx[0] = (u32)(base + ty0 + tz0);
        idx[1] = (u32)(base + ty0 + tz1);
        idx[2] = (u32)(base + ty1 + tz0);
        idx[3] = (u32)(base + ty1 + tz1);
    } else {
        u32 ux = (u32)cx, uy = (u32)cy, uz = (u32)cz;
        u32 ty0 = uy * 2654435761u, ty1 = ty0 + 2654435761u;
        u32 tz0 = uz * 805459861u,  tz1 = tz0 + 805459861u;
        #pragma unroll
        for (int p = 0; p < 4; p++) {
            u32 s = (((p >> 1) & 1) ? ty1 : ty0) ^ ((p & 1) ? tz1 : tz0);
            idx[p] = (ux ^ s) & (TSZ - 1u);
            i1[p]  = ((ux + 1u) ^ s) & (TSZ - 1u);
        }
    }
}

// dense reduce: q[p] = (c0.x, c0.y, c1.x, c1.y)
__device__ __forceinline__ u32 reduce_dense(const float4 q[4], const float w[3]) {
    const float wx = w[0], wy = w[1], wz = w[2];
    const float wx0 = 1.f - wx, wy0 = 1.f - wy, wz0 = 1.f - wz;
    float f0 = 0.f, f1 = 0.f;
    #pragma unroll
    for (int p = 0; p < 4; p++) {
        const int oy = (p >> 1) & 1, oz = p & 1;
        float wyz = (oy ? wy : wy0) * (oz ? wz : wz0);
        float w0 = wx0 * wyz, w1 = wx * wyz;
        f0 = fmaf(w0, q[p].x, fmaf(w1, q[p].z, f0));
        f1 = fmaf(w0, q[p].y, fmaf(w1, q[p].w, f1));
    }
    return f22h2(f1, f0);
}

// hashed reduce with parity select + fallback
__device__ __forceinline__ u32 reduce_hash(const float4 q[4], const float2 e[4],
                                           const u32 i0[4], const u32 i1[4],
                                           const float w[3])
{
    const float wx = w[0], wy = w[1], wz = w[2];
    const float wx0 = 1.f - wx, wy0 = 1.f - wy, wz0 = 1.f - wz;
    float f0 = 0.f, f1 = 0.f;
    #pragma unroll
    for (int p = 0; p < 4; p++) {
        const int oy = (p >> 1) & 1, oz = p & 1;
        const bool hi = (i0[p] & 1u) != 0u;
        float2 c0 = hi ? make_float2(q[p].z, q[p].w) : make_float2(q[p].x, q[p].y);
        float2 ot = hi ? make_float2(q[p].x, q[p].y) : make_float2(q[p].z, q[p].w);
        float2 c1 = ((i0[p] ^ i1[p]) == 1u) ? ot : e[p];
        float wyz = (oy ? wy : wy0) * (oz ? wz : wz0);
        float w0 = wx0 * wyz, w1 = wx * wyz;
        f0 = fmaf(w0, c0.x, fmaf(w1, c1.x, f0));
        f1 = fmaf(w0, c0.y, fmaf(w1, c1.y, f1));
    }
    return f22h2(f1, f0);
}

__global__ void __launch_bounds__(BLOCK, 3)
sdf_kernel(const float* __restrict__ x,
           const float* __restrict__ table,
           const float* __restrict__ w1,
           const float* __restrict__ w2,
           const float* __restrict__ w3,
           const float* __restrict__ w4,
           float* __restrict__ out,
           int n, LvlParams P)
{
    __shared__ __align__(16) __half s_w1[64 * 40];
    __shared__ __align__(16) __half s_w2[64 * 72];
    __shared__ __align__(16) __half s_w3[64 * 72];
    __shared__ float s_w4[64];
    __shared__ __align__(16) __half s_enc[BLOCK * 40]; // row stride 40 halves (80B)

    const int tid  = threadIdx.x;
    const int lane = tid & 31;
    const int warp = tid >> 5;

    // ---- prologue: weights -> fp16 smem ----
    for (int t = tid; t < 64 * 32; t += BLOCK) {
        int nn = t >> 5, kk = t & 31;
        s_w1[nn * 40 + kk] = __float2half_rn(w1[t]);
    }
    for (int t = tid; t < 64 * 64; t += BLOCK) {
        int nn = t >> 6, kk = t & 63;
        s_w2[nn * 72 + kk] = __float2half_rn(w2[t]);
        s_w3[nn * 72 + kk] = __float2half_rn(w3[t]);
    }
    if (tid < 64) s_w4[tid] = w4[tid];
    __syncthreads();

    // ---- encode: level pairs, batched loads; pd table for dense levels ----
    const int i  = blockIdx.x * BLOCK + tid;
    const int ic = (i < n) ? i : (n - 1);
    const float px = x[3 * ic + 0];
    const float py = x[3 * ic + 1];
    const float pz = x[3 * ic + 2];

    u32* encw = reinterpret_cast<u32*>(s_enc);

    #pragma unroll 1
    for (int lp = 0; lp < NLV / 2; lp++) {
        const int lA = 2 * lp, lB = 2 * lp + 1;
        const bool dA = P.dense[lA] != 0, dB = P.dense[lB] != 0;
        u32 iA[4], jA[4], iB[4], jB[4];
        float wA[3], wB[3];
        lvl_setup(px, py, pz, P.scale[lA], P.res[lA], dA, P.pdoff[lA], iA, jA, wA);
        lvl_setup(px, py, pz, P.scale[lB], P.res[lB], dB, P.pdoff[lB], iB, jB, wB);

        const float2* tA = reinterpret_cast<const float2*>(table) + (size_t)lA * TSZ;
        const float2* tB = reinterpret_cast<const float2*>(table) + (size_t)lB * TSZ;
        const float4* t4A = reinterpret_cast<const float4*>(tA);
        const float4* t4B = reinterpret_cast<const float4*>(tB);

        // primary loads (batched: up to 8 LDG.128 in flight)
        float4 qA[4], qB[4];
        #pragma unroll
        for (int p = 0; p < 4; p++)
            qA[p] = dA ? __ldg(&g_pd[iA[p]]) : __ldg(&t4A[iA[p] >> 1]);
        #pragma unroll
        for (int p = 0; p < 4; p++)
            qB[p] = dB ? __ldg(&g_pd[iB[p]]) : __ldg(&t4B[iB[p] >> 1]);

        // fallback loads: hashed levels only, unmerged lanes only
        float2 eA[4], eB[4];
        if (!dA) {
            #pragma unroll
            for (int p = 0; p < 4; p++) {
                eA[p] = make_float2(0.f, 0.f);
                if ((iA[p] ^ jA[p]) != 1u) eA[p] = __ldg(&tA[jA[p]]);
            }
        }
        if (!dB) {
            #pragma unroll
            for (int p = 0; p < 4; p++) {
                eB[p] = make_float2(0.f, 0.f);
                if ((iB[p] ^ jB[p]) != 1u) eB[p] = __ldg(&tB[jB[p]]);
            }
        }

        encw[tid * 20 + lA] = dA ? reduce_dense(qA, wA) : reduce_hash(qA, eA, iA, jA, wA);
        encw[tid * 20 + lB] = dB ? reduce_dense(qB, wB) : reduce_hash(qB, eB, iB, jB, wB);
    }
    __syncwarp();  // enc rows are warp-private

    // ---- MLP on tensor cores: 32 pts/warp, sequential m-tiles (r8-verbatim) ----
    const u32 enc_b = (u32)__cvta_generic_to_shared(s_enc);
    const u32 w1_b  = (u32)__cvta_generic_to_shared(s_w1);
    const u32 w2_b  = (u32)__cvta_generic_to_shared(s_w2);
    const u32 w3_b  = (u32)__cvta_generic_to_shared(s_w3);

    #pragma unroll 1
    for (int mt = 0; mt < 2; mt++) {
        float d[8][4];
        u32   a[4][4];

        // layer 1: 32 -> 64
        #pragma unroll
        for (int kt = 0; kt < 2; kt++) {
            u32 addr = enc_b + (u32)((warp * 32 + mt * 16 + (lane & 15)) * 80
                                     + kt * 32 + (lane >> 4) * 16);
            ldsm4(a[kt][0], a[kt][1], a[kt][2], a[kt][3], addr);
        }
        #pragma unroll
        for (int nt = 0; nt < 8; nt++)
            #pragma unroll
            for (int v = 0; v < 4; v++) d[nt][v] = 0.f;

        #pragma unroll
        for (int kt = 0; kt < 2; kt++)
            #pragma unroll
            for (int u = 0; u < 4; u++) {
                u32 b0, b1, b2, b3;
                u32 addr = w1_b + (u32)((u * 16 + (lane >> 4) * 8 + (lane & 7)) * 80
                                        + kt * 32 + ((lane >> 3) & 1) * 16);
                ldsm4(b0, b1, b2, b3, addr);
                mma16816(d[2 * u],     a[kt], b0, b1);
                mma16816(d[2 * u + 1], a[kt], b2, b3);
            }

        #pragma unroll
        for (int kk = 0; kk < 4; kk++) {
            a[kk][0] = f22h2(softplus10(d[2*kk][1]),   softplus10(d[2*kk][0]));
            a[kk][1] = f22h2(softplus10(d[2*kk][3]),   softplus10(d[2*kk][2]));
            a[kk][2] = f22h2(softplus10(d[2*kk+1][1]), softplus10(d[2*kk+1][0]));
            a[kk][3] = f22h2(softplus10(d[2*kk+1][3]), softplus10(d[2*kk+1][2]));
        }

        // layers 2 and 3: 64 -> 64
        #pragma unroll 1
        for (int layer = 0; layer < 2; layer++) {
            const u32 wb = (layer == 0) ? w2_b : w3_b;
            #pragma unroll
            for (int nt = 0; nt < 8; nt++)
                #pragma unroll
                for (int v = 0; v < 4; v++) d[nt][v] = 0.f;

            #pragma unroll
            for (int kt = 0; kt < 4; kt++)
                #pragma unroll
                for (int u = 0; u < 4; u++) {
                    u32 b0, b1, b2, b3;
                    u32 addr = wb + (u32)((u * 16 + (lane >> 4) * 8 + (lane & 7)) * 144
                                          + kt * 32 + ((lane >> 3) & 1) * 16);
                    ldsm4(b0, b1, b2, b3, addr);
                    mma16816(d[2 * u],     a[kt], b0, b1);
                    mma16816(d[2 * u + 1], a[kt], b2, b3);
                }

            if (layer == 0) {
                #pragma unroll
                for (int kk = 0; kk < 4; kk++) {
                    a[kk][0] = f22h2(softplus10(d[2*kk][1]),   softplus10(d[2*kk][0]));
                    a[kk][1] = f22h2(softplus10(d[2*kk][3]),   softplus10(d[2*kk][2]));
                    a[kk][2] = f22h2(softplus10(d[2*kk+1][1]), softplus10(d[2*kk+1][0]));
                    a[kk][3] = f22h2(softplus10(d[2*kk+1][3]), softplus10(d[2*kk+1][2]));
                }
            }
        }

        // layer 4: 64 -> 1
        {
            float p0 = 0.f, p1 = 0.f;
            #pragma unroll
            for (int nt = 0; nt < 8; nt++) {
                int c = nt * 8 + 2 * (lane & 3);
                float wv0 = s_w4[c], wv1 = s_w4[c + 1];
                p0 = fmaf(softplus10(d[nt][0]), wv0, p0);
                p0 = fmaf(softplus10(d[nt][1]), wv1, p0);
                p1 = fmaf(softplus10(d[nt][2]), wv0, p1);
                p1 = fmaf(softplus10(d[nt][3]), wv1, p1);
            }
            p0 += __shfl_xor_sync(0xffffffffu, p0, 1);
            p0 += __shfl_xor_sync(0xffffffffu, p0, 2);
            p1 += __shfl_xor_sync(0xffffffffu, p1, 1);
            p1 += __shfl_xor_sync(0xffffffffu, p1, 2);
            if ((lane & 3) == 0) {
                int r0 = blockIdx.x * BLOCK + warp * 32 + mt * 16 + (lane >> 2);
                if (r0 < n) out[r0] = p0;
                int r1 = r0 + 8;
                if (r1 < n) out[r1] = p1;
            }
        }
    }
}

extern "C" void kernel_launch(void* const* d_in, const int* in_sizes, int n_in,
                              void* d_out, int out_size)
{
    const float* x     = (const float*)d_in[0];
    const float* table = (const float*)d_in[1];
    const float* w1    = (const float*)d_in[2];
    const float* w2    = (const float*)d_in[3];
    const float* w3    = (const float*)d_in[4];
    const float* w4    = (const float*)d_in[5];
    float* out = (float*)d_out;

    const int n = in_sizes[0] / 3;

    LvlParams P;
    BuildParams B;
    B.nd = 0; B.total = 0;
    const double pls = exp2(7.0 / 15.0);
    const double l2s = log2(pls);
    for (int l = 0; l < NLV; l++) {
        double s = exp2((double)l * l2s) * 16.0 - 1.0;
        P.scale[l] = (float)s;
        long long r = (long long)ceil(s) + 1;
        P.res[l] = (int)r;
        bool dn = (r * r * r <= (long long)TSZ);
        P.pdoff[l] = 0;
        P.dense[l] = 0;
        if (dn && B.nd < 8) {
            long long cnt = r * r * r;
            if (B.total + cnt <= PD_CAP) {
                P.dense[l] = 1;
                P.pdoff[l] = B.total;
                B.lvl[B.nd] = l;
                B.res[B.nd] = (int)r;
                B.off[B.nd] = B.total;
                B.nd++;
                B.total += (int)cnt;
            }
            // else: treated as hashed — impossible for these params, and the
            // hashed path would be wrong for a dense level; params are static.
        }
    }

    if (B.total > 0) {
        int bgrid = (B.total + 255) / 256;
        build_pd<<<bgrid, 256>>>(table, B);
    }

    int grid = (n + BLOCK - 1) / BLOCK;
    sdf_kernel<<<grid, BLOCK>>>(x, table, w1, w2, w3, w4, out, n, P);
}

// round 12
// speedup vs baseline: 1.9323x; 1.2532x over previous
#include <cuda_runtime.h>
#include <cuda_fp16.h>
#include <math.h>
#include <stdint.h>

#define NLV   16
#define TBITS 19
#define TSZ   (1u << TBITS)
#define BLOCK 256
#define PD_CAP 393216   // dense pair-table capacity (entries); actual 330940

typedef unsigned int u32;

struct LvlParams {
    float scale[NLV];
    int   res[NLV];
    int   pdoff[NLV];   // valid for dense levels 0..4
};

struct BuildParams {
    int lvl[8];
    int res[8];
    int off[8];
    int nd;
    int total;
};

// dense pair-table: entry pdoff[l]+j holds (T[j].x, T[j].y, T[j+1x,clamped].x, .y)
__device__ __align__(16) float4 g_pd[PD_CAP];

// softplus(10z)/10 = max(z,0) + (ln2/10)*lg2(1 + 2^(-10*log2e*|z|))
__device__ __forceinline__ float softplus10(float z) {
    float e, l;
    float a = -14.426950408889634f * fabsf(z);
    asm("ex2.approx.ftz.f32 %0, %1;" : "=f"(e) : "f"(a));
    float p = 1.0f + e;
    asm("lg2.approx.ftz.f32 %0, %1;" : "=f"(l) : "f"(p));
    return fmaf(l, 0.069314718055994531f, fmaxf(z, 0.0f));
}

__device__ __forceinline__ u32 f22h2(float hi, float lo) {
    u32 r;
    asm("cvt.rn.f16x2.f32 %0, %1, %2;" : "=r"(r) : "f"(hi), "f"(lo));
    return r;
}

__device__ __forceinline__ void ldsm4(u32& r0, u32& r1, u32& r2, u32& r3, u32 addr) {
    asm volatile("ldmatrix.sync.aligned.m8n8.x4.shared.b16 {%0,%1,%2,%3}, [%4];"
        : "=r"(r0), "=r"(r1), "=r"(r2), "=r"(r3) : "r"(addr));
}

__device__ __forceinline__ void mma16816(float* d, const u32* a, u32 b0, u32 b1) {
    asm volatile("mma.sync.aligned.m16n8k16.row.col.f32.f16.f16.f32 "
        "{%0,%1,%2,%3},{%4,%5,%6,%7},{%8,%9},{%0,%1,%2,%3};"
        : "+f"(d[0]), "+f"(d[1]), "+f"(d[2]), "+f"(d[3])
        : "r"(a[0]), "r"(a[1]), "r"(a[2]), "r"(a[3]), "r"(b0), "r"(b1));
}

// =============== build kernel: dense pair-table ===============
__global__ void build_pd(const float* __restrict__ table, BuildParams B)
{
    int f = blockIdx.x * blockDim.x + threadIdx.x;
    if (f >= B.total) return;
    int l = 0, res = 1, j = f;
    #pragma unroll
    for (int d = 0; d < 8; d++) {
        if (d < B.nd && f >= B.off[d]) { l = B.lvl[d]; res = B.res[d]; j = f - B.off[d]; }
    }
    const float2* t2 = reinterpret_cast<const float2*>(table) + (size_t)l * TSZ;
    int qx = j % res;
    float2 c0 = __ldg(&t2[j]);
    float2 c1 = __ldg(&t2[(qx < res - 1) ? j + 1 : j]);
    g_pd[f] = make_float4(c0.x, c0.y, c1.x, c1.y);
}

// ---- dense level: pd-table indices (4 entries) + weights ----
__device__ __forceinline__ void dense_setup(float px, float py, float pz,
                                            float sc, int res, int pdoff,
                                            int idx[4], float w[3])
{
    float fx = px * sc + 0.5f, fy = py * sc + 0.5f, fz = pz * sc + 0.5f;
    float gx = floorf(fx), gy = floorf(fy), gz = floorf(fz);
    w[0] = fx - gx; w[1] = fy - gy; w[2] = fz - gz;
    int cx = (int)gx, cy = (int)gy, cz = (int)gz;

    int jx  = min(max(cx, 0), res - 1);
    int ty0 = min(max(cy,     0), res - 1) * res;
    int ty1 = min(max(cy + 1, 0), res - 1) * res;
    int tz0 = min(max(cz,     0), res - 1) * (res * res);
    int tz1 = min(max(cz + 1, 0), res - 1) * (res * res);
    int base = pdoff + jx;
    idx[0] = base + ty0 + tz0;
    idx[1] = base + ty0 + tz1;
    idx[2] = base + ty1 + tz0;
    idx[3] = base + ty1 + tz1;
}

__device__ __forceinline__ u32 reduce_dense(const float4 q[4], const float w[3]) {
    const float wx = w[0], wy = w[1], wz = w[2];
    const float wx0 = 1.f - wx, wy0 = 1.f - wy, wz0 = 1.f - wz;
    float f0 = 0.f, f1 = 0.f;
    #pragma unroll
    for (int p = 0; p < 4; p++) {
        const int oy = (p >> 1) & 1, oz = p & 1;
        float wyz = (oy ? wy : wy0) * (oz ? wz : wz0);
        float w0 = wx0 * wyz, w1 = wx * wyz;
        f0 = fmaf(w0, q[p].x, fmaf(w1, q[p].z, f0));
        f1 = fmaf(w0, q[p].y, fmaf(w1, q[p].w, f1));
    }
    return f22h2(f1, f0);
}

// ---- hashed level: paired-corner indices + weights (r8-proven) ----
__device__ __forceinline__ void hash_setup(float px, float py, float pz,
                                           float sc, u32 i0[4], u32 i1[4], float w[3])
{
    float fx = px * sc + 0.5f, fy = py * sc + 0.5f, fz = pz * sc + 0.5f;
    float gx = floorf(fx), gy = floorf(fy), gz = floorf(fz);
    w[0] = fx - gx; w[1] = fy - gy; w[2] = fz - gz;
    u32 ux = (u32)(int)gx, uy = (u32)(int)gy, uz = (u32)(int)gz;
    u32 ty0 = uy * 2654435761u, ty1 = ty0 + 2654435761u;
    u32 tz0 = uz * 805459861u,  tz1 = tz0 + 805459861u;
    #pragma unroll
    for (int p = 0; p < 4; p++) {
        u32 s = (((p >> 1) & 1) ? ty1 : ty0) ^ ((p & 1) ? tz1 : tz0);
        i0[p] = (ux ^ s) & (TSZ - 1u);
        i1[p] = ((ux + 1u) ^ s) & (TSZ - 1u);
    }
}

__device__ __forceinline__ u32 reduce_hash(const float4 q[4], const float2 e[4],
                                           const u32 i0[4], const u32 i1[4],
                                           const float w[3])
{
    const float wx = w[0], wy = w[1], wz = w[2];
    const float wx0 = 1.f - wx, wy0 = 1.f - wy, wz0 = 1.f - wz;
    float f0 = 0.f, f1 = 0.f;
    #pragma unroll
    for (int p = 0; p < 4; p++) {
        const int oy = (p >> 1) & 1, oz = p & 1;
        const bool hi = (i0[p] & 1u) != 0u;
        float2 c0 = hi ? make_float2(q[p].z, q[p].w) : make_float2(q[p].x, q[p].y);
        float2 ot = hi ? make_float2(q[p].x, q[p].y) : make_float2(q[p].z, q[p].w);
        float2 c1 = ((i0[p] ^ i1[p]) == 1u) ? ot : e[p];
        float wyz = (oy ? wy : wy0) * (oz ? wz : wz0);
        float w0 = wx0 * wyz, w1 = wx * wyz;
        f0 = fmaf(w0, c0.x, fmaf(w1, c1.x, f0));
        f1 = fmaf(w0, c0.y, fmaf(w1, c1.y, f1));
    }
    return f22h2(f1, f0);
}

__global__ void __launch_bounds__(BLOCK, 3)
sdf_kernel(const float* __restrict__ x,
           const float* __restrict__ table,
           const float* __restrict__ w1,
           const float* __restrict__ w2,
           const float* __restrict__ w3,
           const float* __restrict__ w4,
           float* __restrict__ out,
           int n, LvlParams P)
{
    __shared__ __align__(16) __half s_w1[64 * 40];
    __shared__ __align__(16) __half s_w2[64 * 72];
    __shared__ __align__(16) __half s_w3[64 * 72];
    __shared__ float s_w4[64];
    __shared__ __align__(16) __half s_enc[BLOCK * 40]; // row stride 40 halves (80B)

    const int tid  = threadIdx.x;
    const int lane = tid & 31;
    const int warp = tid >> 5;

    // ---- prologue: weights -> fp16 smem ----
    for (int t = tid; t < 64 * 32; t += BLOCK) {
        int nn = t >> 5, kk = t & 31;
        s_w1[nn * 40 + kk] = __float2half_rn(w1[t]);
    }
    for (int t = tid; t < 64 * 64; t += BLOCK) {
        int nn = t >> 6, kk = t & 63;
        s_w2[nn * 72 + kk] = __float2half_rn(w2[t]);
        s_w3[nn * 72 + kk] = __float2half_rn(w3[t]);
    }
    if (tid < 64) s_w4[tid] = w4[tid];
    __syncthreads();

    const int i  = blockIdx.x * BLOCK + tid;
    const int ic = (i < n) ? i : (n - 1);
    const float px = x[3 * ic + 0];
    const float py = x[3 * ic + 1];
    const float pz = x[3 * ic + 2];

    u32* encw = reinterpret_cast<u32*>(s_enc);

    // ---- dense levels 0..2: 12 back-to-back LDG.128 from pd table ----
    {
        int i0[4], i1[4], i2[4];
        float w0[3], w1v[3], w2v[3];
        dense_setup(px, py, pz, P.scale[0], P.res[0], P.pdoff[0], i0, w0);
        dense_setup(px, py, pz, P.scale[1], P.res[1], P.pdoff[1], i1, w1v);
        dense_setup(px, py, pz, P.scale[2], P.res[2], P.pdoff[2], i2, w2v);

        float4 q0[4], q1[4], q2[4];
        #pragma unroll
        for (int p = 0; p < 4; p++) q0[p] = __ldg(&g_pd[i0[p]]);
        #pragma unroll
        for (int p = 0; p < 4; p++) q1[p] = __ldg(&g_pd[i1[p]]);
        #pragma unroll
        for (int p = 0; p < 4; p++) q2[p] = __ldg(&g_pd[i2[p]]);

        encw[tid * 20 + 0] = reduce_dense(q0, w0);
        encw[tid * 20 + 1] = reduce_dense(q1, w1v);
        encw[tid * 20 + 2] = reduce_dense(q2, w2v);
    }

    // ---- dense levels 3..4: 8 back-to-back LDG.128 ----
    {
        int i3[4], i4[4];
        float w3v[3], w4v[3];
        dense_setup(px, py, pz, P.scale[3], P.res[3], P.pdoff[3], i3, w3v);
        dense_setup(px, py, pz, P.scale[4], P.res[4], P.pdoff[4], i4, w4v);

        float4 q3[4], q4[4];
        #pragma unroll
        for (int p = 0; p < 4; p++) q3[p] = __ldg(&g_pd[i3[p]]);
        #pragma unroll
        for (int p = 0; p < 4; p++) q4[p] = __ldg(&g_pd[i4[p]]);

        encw[tid * 20 + 3] = reduce_dense(q3, w3v);
        encw[tid * 20 + 4] = reduce_dense(q4, w4v);
    }

    // ---- hashed level pairs (5,6)(7,8)(9,10)(11,12)(13,14): r8-style batching ----
    #pragma unroll 1
    for (int lp = 0; lp < 5; lp++) {
        const int lA = 5 + 2 * lp, lB = lA + 1;
        u32 iA[4], jA[4], iB[4], jB[4];
        float wA[3], wB[3];
        hash_setup(px, py, pz, P.scale[lA], iA, jA, wA);
        hash_setup(px, py, pz, P.scale[lB], iB, jB, wB);

        const float2* tA = reinterpret_cast<const float2*>(table) + (size_t)lA * TSZ;
        const float2* tB = reinterpret_cast<const float2*>(table) + (size_t)lB * TSZ;
        const float4* t4A = reinterpret_cast<const float4*>(tA);
        const float4* t4B = reinterpret_cast<const float4*>(tB);

        float4 qA[4], qB[4];
        #pragma unroll
        for (int p = 0; p < 4; p++) qA[p] = __ldg(&t4A[iA[p] >> 1]);
        #pragma unroll
        for (int p = 0; p < 4; p++) qB[p] = __ldg(&t4B[iB[p] >> 1]);

        float2 eA[4], eB[4];
        #pragma unroll
        for (int p = 0; p < 4; p++) {
            eA[p] = make_float2(0.f, 0.f);
            if ((iA[p] ^ jA[p]) != 1u) eA[p] = __ldg(&tA[jA[p]]);
        }
        #pragma unroll
        for (int p = 0; p < 4; p++) {
            eB[p] = make_float2(0.f, 0.f);
            if ((iB[p] ^ jB[p]) != 1u) eB[p] = __ldg(&tB[jB[p]]);
        }

        encw[tid * 20 + lA] = reduce_hash(qA, eA, iA, jA, wA);
        encw[tid * 20 + lB] = reduce_hash(qB, eB, iB, jB, wB);
    }

    // ---- hashed level 15 (single) ----
    {
        u32 i15[4], j15[4];
        float w15[3];
        hash_setup(px, py, pz, P.scale[15], i15, j15, w15);
        const float2* t2 = reinterpret_cast<const float2*>(table) + (size_t)15 * TSZ;
        const float4* t4 = reinterpret_cast<const float4*>(t2);

        float4 q[4];
        #pragma unroll
        for (int p = 0; p < 4; p++) q[p] = __ldg(&t4[i15[p] >> 1]);
        float2 e[4];
        #pragma unroll
        for (int p = 0; p < 4; p++) {
            e[p] = make_float2(0.f, 0.f);
            if ((i15[p] ^ j15[p]) != 1u) e[p] = __ldg(&t2[j15[p]]);
        }
        encw[tid * 20 + 15] = reduce_hash(q, e, i15, j15, w15);
    }
    __syncwarp();  // enc rows are warp-private

    // ---- MLP on tensor cores: 32 pts/warp, sequential m-tiles (r8-verbatim) ----
    const u32 enc_b = (u32)__cvta_generic_to_shared(s_enc);
    const u32 w1_b  = (u32)__cvta_generic_to_shared(s_w1);
    const u32 w2_b  = (u32)__cvta_generic_to_shared(s_w2);
    const u32 w3_b  = (u32)__cvta_generic_to_shared(s_w3);

    #pragma unroll 1
    for (int mt = 0; mt < 2; mt++) {
        float d[8][4];
        u32   a[4][4];

        // layer 1: 32 -> 64
        #pragma unroll
        for (int kt = 0; kt < 2; kt++) {
            u32 addr = enc_b + (u32)((warp * 32 + mt * 16 + (lane & 15)) * 80
                                     + kt * 32 + (lane >> 4) * 16);
            ldsm4(a[kt][0], a[kt][1], a[kt][2], a[kt][3], addr);
        }
        #pragma unroll
        for (int nt = 0; nt < 8; nt++)
            #pragma unroll
            for (int v = 0; v < 4; v++) d[nt][v] = 0.f;

        #pragma unroll
        for (int kt = 0; kt < 2; kt++)
            #pragma unroll
            for (int u = 0; u < 4; u++) {
                u32 b0, b1, b2, b3;
                u32 addr = w1_b + (u32)((u * 16 + (lane >> 4) * 8 + (lane & 7)) * 80
                                        + kt * 32 + ((lane >> 3) & 1) * 16);
                ldsm4(b0, b1, b2, b3, addr);
                mma16816(d[2 * u],     a[kt], b0, b1);
                mma16816(d[2 * u + 1], a[kt], b2, b3);
            }

        #pragma unroll
        for (int kk = 0; kk < 4; kk++) {
            a[kk][0] = f22h2(softplus10(d[2*kk][1]),   softplus10(d[2*kk][0]));
            a[kk][1] = f22h2(softplus10(d[2*kk][3]),   softplus10(d[2*kk][2]));
            a[kk][2] = f22h2(softplus10(d[2*kk+1][1]), softplus10(d[2*kk+1][0]));
            a[kk][3] = f22h2(softplus10(d[2*kk+1][3]), softplus10(d[2*kk+1][2]));
        }

        // layers 2 and 3: 64 -> 64
        #pragma unroll 1
        for (int layer = 0; layer < 2; layer++) {
            const u32 wb = (layer == 0) ? w2_b : w3_b;
            #pragma unroll
            for (int nt = 0; nt < 8; nt++)
                #pragma unroll
                for (int v = 0; v < 4; v++) d[nt][v] = 0.f;

            #pragma unroll
            for (int kt = 0; kt < 4; kt++)
                #pragma unroll
                for (int u = 0; u < 4; u++) {
                    u32 b0, b1, b2, b3;
                    u32 addr = wb + (u32)((u * 16 + (lane >> 4) * 8 + (lane & 7)) * 144
                                          + kt * 32 + ((lane >> 3) & 1) * 16);
                    ldsm4(b0, b1, b2, b3, addr);
                    mma16816(d[2 * u],     a[kt], b0, b1);
                    mma16816(d[2 * u + 1], a[kt], b2, b3);
                }

            if (layer == 0) {
                #pragma unroll
                for (int kk = 0; kk < 4; kk++) {
                    a[kk][0] = f22h2(softplus10(d[2*kk][1]),   softplus10(d[2*kk][0]));
                    a[kk][1] = f22h2(softplus10(d[2*kk][3]),   softplus10(d[2*kk][2]));
                    a[kk][2] = f22h2(softplus10(d[2*kk+1][1]), softplus10(d[2*kk+1][0]));
                    a[kk][3] = f22h2(softplus10(d[2*kk+1][3]), softplus10(d[2*kk+1][2]));
                }
            }
        }

        // layer 4: 64 -> 1
        {
            float p0 = 0.f, p1 = 0.f;
            #pragma unroll
            for (int nt = 0; nt < 8; nt++) {
                int c = nt * 8 + 2 * (lane & 3);
                float wv0 = s_w4[c], wv1 = s_w4[c + 1];
                p0 = fmaf(softplus10(d[nt][0]), wv0, p0);
                p0 = fmaf(softplus10(d[nt][1]), wv1, p0);
                p1 = fmaf(softplus10(d[nt][2]), wv0, p1);
                p1 = fmaf(softplus10(d[nt][3]), wv1, p1);
            }
            p0 += __shfl_xor_sync(0xffffffffu, p0, 1);
            p0 += __shfl_xor_sync(0xffffffffu, p0, 2);
            p1 += __shfl_xor_sync(0xffffffffu, p1, 1);
            p1 += __shfl_xor_sync(0xffffffffu, p1, 2);
            if ((lane & 3) == 0) {
                int r0 = blockIdx.x * BLOCK + warp * 32 + mt * 16 + (lane >> 2);
                if (r0 < n) out[r0] = p0;
                int r1 = r0 + 8;
                if (r1 < n) out[r1] = p1;
            }
        }
    }
}

extern "C" void kernel_launch(void* const* d_in, const int* in_sizes, int n_in,
                              void* d_out, int out_size)
{
    const float* x     = (const float*)d_in[0];
    const float* table = (const float*)d_in[1];
    const float* w1    = (const float*)d_in[2];
    const float* w2    = (const float*)d_in[3];
    const float* w3    = (const float*)d_in[4];
    const float* w4    = (const float*)d_in[5];
    float* out = (float*)d_out;

    const int n = in_sizes[0] / 3;

    LvlParams P;
    BuildParams B;
    B.nd = 0; B.total = 0;
    const double pls = exp2(7.0 / 15.0);
    const double l2s = log2(pls);
    for (int l = 0; l < NLV; l++) {
        double s = exp2((double)l * l2s) * 16.0 - 1.0;
        P.scale[l] = (float)s;
        long long r = (long long)ceil(s) + 1;
        P.res[l] = (int)r;
        P.pdoff[l] = 0;
        bool dn = (r * r * r <= (long long)TSZ);
        if (dn && B.nd < 8 && B.total + r * r * r <= PD_CAP) {
            P.pdoff[l] = B.total;
            B.lvl[B.nd] = l;
            B.res[B.nd] = (int)r;
            B.off[B.nd] = B.total;
            B.nd++;
            B.total += (int)(r * r * r);
        }
    }

    if (B.total > 0) {
        int bgrid = (B.total + 255) / 256;
        build_pd<<<bgrid, 256>>>(table, B);
    }

    int grid = (n + BLOCK - 1) / BLOCK;
    sdf_kernel<<<grid, BLOCK>>>(x, table, w1, w2, w3, w4, out, n, P);
}

// round 13
// speedup vs baseline: 1.9349x; 1.0013x over previous
#include <cuda_runtime.h>
#include <cuda_fp16.h>
#include <math.h>
#include <stdint.h>

#define NLV   16
#define TBITS 19
#define TSZ   (1u << TBITS)
#define BLOCK 256
#define PD_CAP 393216   // dense pair-table capacity (entries); actual 330940

typedef unsigned int u32;

struct LvlParams {
    float scale[NLV];
    int   res[NLV];
    int   pdoff[NLV];   // valid for dense levels 0..4
};

struct BuildParams {
    int lvl[8];
    int res[8];
    int off[8];
    int nd;
    int total;
};

// dense pair-table: entry pdoff[l]+j holds (T[j].x, T[j].y, T[j+1x,clamped].x, .y)
__device__ __align__(16) float4 g_pd[PD_CAP];

// softplus(10z)/10 = max(z,0) + (ln2/10)*lg2(1 + 2^(-10*log2e*|z|))
__device__ __forceinline__ float softplus10(float z) {
    float e, l;
    float a = -14.426950408889634f * fabsf(z);
    asm("ex2.approx.ftz.f32 %0, %1;" : "=f"(e) : "f"(a));
    float p = 1.0f + e;
    asm("lg2.approx.ftz.f32 %0, %1;" : "=f"(l) : "f"(p));
    return fmaf(l, 0.069314718055994531f, fmaxf(z, 0.0f));
}

__device__ __forceinline__ u32 f22h2(float hi, float lo) {
    u32 r;
    asm("cvt.rn.f16x2.f32 %0, %1, %2;" : "=r"(r) : "f"(hi), "f"(lo));
    return r;
}

__device__ __forceinline__ void ldsm4(u32& r0, u32& r1, u32& r2, u32& r3, u32 addr) {
    asm volatile("ldmatrix.sync.aligned.m8n8.x4.shared.b16 {%0,%1,%2,%3}, [%4];"
        : "=r"(r0), "=r"(r1), "=r"(r2), "=r"(r3) : "r"(addr));
}

__device__ __forceinline__ void mma16816(float* d, const u32* a, u32 b0, u32 b1) {
    asm volatile("mma.sync.aligned.m16n8k16.row.col.f32.f16.f16.f32 "
        "{%0,%1,%2,%3},{%4,%5,%6,%7},{%8,%9},{%0,%1,%2,%3};"
        : "+f"(d[0]), "+f"(d[1]), "+f"(d[2]), "+f"(d[3])
        : "r"(a[0]), "r"(a[1]), "r"(a[2]), "r"(a[3]), "r"(b0), "r"(b1));
}

// =============== build kernel: dense pair-table ===============
__global__ void build_pd(const float* __restrict__ table, BuildParams B)
{
    int f = blockIdx.x * blockDim.x + threadIdx.x;
    if (f >= B.total) return;
    int l = 0, res = 1, j = f;
    #pragma unroll
    for (int d = 0; d < 8; d++) {
        if (d < B.nd && f >= B.off[d]) { l = B.lvl[d]; res = B.res[d]; j = f - B.off[d]; }
    }
    const float2* t2 = reinterpret_cast<const float2*>(table) + (size_t)l * TSZ;
    int qx = j % res;
    float2 c0 = __ldg(&t2[j]);
    float2 c1 = __ldg(&t2[(qx < res - 1) ? j + 1 : j]);
    g_pd[f] = make_float4(c0.x, c0.y, c1.x, c1.y);
}

// ---- dense level: pd-table indices (4 entries) + weights ----
__device__ __forceinline__ void dense_setup(float px, float py, float pz,
                                            float sc, int res, int pdoff,
                                            int idx[4], float w[3])
{
    float fx = px * sc + 0.5f, fy = py * sc + 0.5f, fz = pz * sc + 0.5f;
    float gx = floorf(fx), gy = floorf(fy), gz = floorf(fz);
    w[0] = fx - gx; w[1] = fy - gy; w[2] = fz - gz;
    int cx = (int)gx, cy = (int)gy, cz = (int)gz;

    int jx  = min(max(cx, 0), res - 1);
    int ty0 = min(max(cy,     0), res - 1) * res;
    int ty1 = min(max(cy + 1, 0), res - 1) * res;
    int tz0 = min(max(cz,     0), res - 1) * (res * res);
    int tz1 = min(max(cz + 1, 0), res - 1) * (res * res);
    int base = pdoff + jx;
    idx[0] = base + ty0 + tz0;
    idx[1] = base + ty0 + tz1;
    idx[2] = base + ty1 + tz0;
    idx[3] = base + ty1 + tz1;
}

__device__ __forceinline__ u32 reduce_dense(const float4 q[4], const float w[3]) {
    const float wx = w[0], wy = w[1], wz = w[2];
    const float wx0 = 1.f - wx, wy0 = 1.f - wy, wz0 = 1.f - wz;
    float f0 = 0.f, f1 = 0.f;
    #pragma unroll
    for (int p = 0; p < 4; p++) {
        const int oy = (p >> 1) & 1, oz = p & 1;
        float wyz = (oy ? wy : wy0) * (oz ? wz : wz0);
        float w0 = wx0 * wyz, w1 = wx * wyz;
        f0 = fmaf(w0, q[p].x, fmaf(w1, q[p].z, f0));
        f1 = fmaf(w0, q[p].y, fmaf(w1, q[p].w, f1));
    }
    return f22h2(f1, f0);
}

// ---- hashed level: paired-corner indices + weights (r8-proven) ----
__device__ __forceinline__ void hash_setup(float px, float py, float pz,
                                           float sc, u32 i0[4], u32 i1[4], float w[3])
{
    float fx = px * sc + 0.5f, fy = py * sc + 0.5f, fz = pz * sc + 0.5f;
    float gx = floorf(fx), gy = floorf(fy), gz = floorf(fz);
    w[0] = fx - gx; w[1] = fy - gy; w[2] = fz - gz;
    u32 ux = (u32)(int)gx, uy = (u32)(int)gy, uz = (u32)(int)gz;
    u32 ty0 = uy * 2654435761u, ty1 = ty0 + 2654435761u;
    u32 tz0 = uz * 805459861u,  tz1 = tz0 + 805459861u;
    #pragma unroll
    for (int p = 0; p < 4; p++) {
        u32 s = (((p >> 1) & 1) ? ty1 : ty0) ^ ((p & 1) ? tz1 : tz0);
        i0[p] = (ux ^ s) & (TSZ - 1u);
        i1[p] = ((ux + 1u) ^ s) & (TSZ - 1u);
    }
}

__device__ __forceinline__ u32 reduce_hash(const float4 q[4], const float2 e[4],
                                           const u32 i0[4], const u32 i1[4],
                                           const float w[3])
{
    const float wx = w[0], wy = w[1], wz = w[2];
    const float wx0 = 1.f - wx, wy0 = 1.f - wy, wz0 = 1.f - wz;
    float f0 = 0.f, f1 = 0.f;
    #pragma unroll
    for (int p = 0; p < 4; p++) {
        const int oy = (p >> 1) & 1, oz = p & 1;
        const bool hi = (i0[p] & 1u) != 0u;
        float2 c0 = hi ? make_float2(q[p].z, q[p].w) : make_float2(q[p].x, q[p].y);
        float2 ot = hi ? make_float2(q[p].x, q[p].y) : make_float2(q[p].z, q[p].w);
        float2 c1 = ((i0[p] ^ i1[p]) == 1u) ? ot : e[p];
        float wyz = (oy ? wy : wy0) * (oz ? wz : wz0);
        float w0 = wx0 * wyz, w1 = wx * wyz;
        f0 = fmaf(w0, c0.x, fmaf(w1, c1.x, f0));
        f1 = fmaf(w0, c0.y, fmaf(w1, c1.y, f1));
    }
    return f22h2(f1, f0);
}

__global__ void __launch_bounds__(BLOCK, 3)
sdf_kernel(const float* __restrict__ x,
           const float* __restrict__ table,
           const float* __restrict__ w1,
           const float* __restrict__ w2,
           const float* __restrict__ w3,
           const float* __restrict__ w4,
           float* __restrict__ out,
           int n, LvlParams P)
{
    __shared__ __align__(16) __half s_w1[64 * 40];
    __shared__ __align__(16) __half s_w2[64 * 72];
    __shared__ __align__(16) __half s_w3[64 * 72];
    __shared__ float s_w4[64];
    __shared__ __align__(16) __half s_enc[BLOCK * 40]; // row stride 40 halves (80B)

    const int tid  = threadIdx.x;
    const int lane = tid & 31;
    const int warp = tid >> 5;

    // ---- prologue: weights -> fp16 smem ----
    for (int t = tid; t < 64 * 32; t += BLOCK) {
        int nn = t >> 5, kk = t & 31;
        s_w1[nn * 40 + kk] = __float2half_rn(w1[t]);
    }
    for (int t = tid; t < 64 * 64; t += BLOCK) {
        int nn = t >> 6, kk = t & 63;
        s_w2[nn * 72 + kk] = __float2half_rn(w2[t]);
        s_w3[nn * 72 + kk] = __float2half_rn(w3[t]);
    }
    if (tid < 64) s_w4[tid] = w4[tid];
    __syncthreads();

    const int i  = blockIdx.x * BLOCK + tid;
    const int ic = (i < n) ? i : (n - 1);
    const float px = x[3 * ic + 0];
    const float py = x[3 * ic + 1];
    const float pz = x[3 * ic + 2];

    u32* encw = reinterpret_cast<u32*>(s_enc);

    // ---- dense levels 0..2: 12 back-to-back LDG.128 from pd table ----
    {
        int i0[4], i1[4], i2[4];
        float w0[3], w1v[3], w2v[3];
        dense_setup(px, py, pz, P.scale[0], P.res[0], P.pdoff[0], i0, w0);
        dense_setup(px, py, pz, P.scale[1], P.res[1], P.pdoff[1], i1, w1v);
        dense_setup(px, py, pz, P.scale[2], P.res[2], P.pdoff[2], i2, w2v);

        float4 q0[4], q1[4], q2[4];
        #pragma unroll
        for (int p = 0; p < 4; p++) q0[p] = __ldg(&g_pd[i0[p]]);
        #pragma unroll
        for (int p = 0; p < 4; p++) q1[p] = __ldg(&g_pd[i1[p]]);
        #pragma unroll
        for (int p = 0; p < 4; p++) q2[p] = __ldg(&g_pd[i2[p]]);

        encw[tid * 20 + 0] = reduce_dense(q0, w0);
        encw[tid * 20 + 1] = reduce_dense(q1, w1v);
        encw[tid * 20 + 2] = reduce_dense(q2, w2v);
    }

    // ---- dense levels 3..4: 8 back-to-back LDG.128 ----
    {
        int i3[4], i4[4];
        float w3v[3], w4v[3];
        dense_setup(px, py, pz, P.scale[3], P.res[3], P.pdoff[3], i3, w3v);
        dense_setup(px, py, pz, P.scale[4], P.res[4], P.pdoff[4], i4, w4v);

        float4 q3[4], q4[4];
        #pragma unroll
        for (int p = 0; p < 4; p++) q3[p] = __ldg(&g_pd[i3[p]]);
        #pragma unroll
        for (int p = 0; p < 4; p++) q4[p] = __ldg(&g_pd[i4[p]]);

        encw[tid * 20 + 3] = reduce_dense(q3, w3v);
        encw[tid * 20 + 4] = reduce_dense(q4, w4v);
    }

    // ---- hashed level pairs (5,6)(7,8)(9,10)(11,12)(13,14): r8-style batching ----
    #pragma unroll 1
    for (int lp = 0; lp < 5; lp++) {
        const int lA = 5 + 2 * lp, lB = lA + 1;
        u32 iA[4], jA[4], iB[4], jB[4];
        float wA[3], wB[3];
        hash_setup(px, py, pz, P.scale[lA], iA, jA, wA);
        hash_setup(px, py, pz, P.scale[lB], iB, jB, wB);

        const float2* tA = reinterpret_cast<const float2*>(table) + (size_t)lA * TSZ;
        const float2* tB = reinterpret_cast<const float2*>(table) + (size_t)lB * TSZ;
        const float4* t4A = reinterpret_cast<const float4*>(tA);
        const float4* t4B = reinterpret_cast<const float4*>(tB);

        float4 qA[4], qB[4];
        #pragma unroll
        for (int p = 0; p < 4; p++) qA[p] = __ldg(&t4A[iA[p] >> 1]);
        #pragma unroll
        for (int p = 0; p < 4; p++) qB[p] = __ldg(&t4B[iB[p] >> 1]);

        float2 eA[4], eB[4];
        #pragma unroll
        for (int p = 0; p < 4; p++) {
            eA[p] = make_float2(0.f, 0.f);
            if ((iA[p] ^ jA[p]) != 1u) eA[p] = __ldg(&tA[jA[p]]);
        }
        #pragma unroll
        for (int p = 0; p < 4; p++) {
            eB[p] = make_float2(0.f, 0.f);
            if ((iB[p] ^ jB[p]) != 1u) eB[p] = __ldg(&tB[jB[p]]);
        }

        encw[tid * 20 + lA] = reduce_hash(qA, eA, iA, jA, wA);
        encw[tid * 20 + lB] = reduce_hash(qB, eB, iB, jB, wB);
    }

    // ---- hashed level 15 (single) ----
    {
        u32 i15[4], j15[4];
        float w15[3];
        hash_setup(px, py, pz, P.scale[15], i15, j15, w15);
        const float2* t2 = reinterpret_cast<const float2*>(table) + (size_t)15 * TSZ;
        const float4* t4 = reinterpret_cast<const float4*>(t2);

        float4 q[4];
        #pragma unroll
        for (int p = 0; p < 4; p++) q[p] = __ldg(&t4[i15[p] >> 1]);
        float2 e[4];
        #pragma unroll
        for (int p = 0; p < 4; p++) {
            e[p] = make_float2(0.f, 0.f);
            if ((i15[p] ^ j15[p]) != 1u) e[p] = __ldg(&t2[j15[p]]);
        }
        encw[tid * 20 + 15] = reduce_hash(q, e, i15, j15, w15);
    }
    __syncwarp();  // enc rows are warp-private

    // ---- MLP on tensor cores: 32 pts/warp, sequential m-tiles (r8-verbatim) ----
    const u32 enc_b = (u32)__cvta_generic_to_shared(s_enc);
    const u32 w1_b  = (u32)__cvta_generic_to_shared(s_w1);
    const u32 w2_b  = (u32)__cvta_generic_to_shared(s_w2);
    const u32 w3_b  = (u32)__cvta_generic_to_shared(s_w3);

    #pragma unroll 1
    for (int mt = 0; mt < 2; mt++) {
        float d[8][4];
        u32   a[4][4];

        // layer 1: 32 -> 64
        #pragma unroll
        for (int kt = 0; kt < 2; kt++) {
            u32 addr = enc_b + (u32)((warp * 32 + mt * 16 + (lane & 15)) * 80
                                     + kt * 32 + (lane >> 4) * 16);
            ldsm4(a[kt][0], a[kt][1], a[kt][2], a[kt][3], addr);
        }
        #pragma unroll
        for (int nt = 0; nt < 8; nt++)
            #pragma unroll
            for (int v = 0; v < 4; v++) d[nt][v] = 0.f;

        #pragma unroll
        for (int kt = 0; kt < 2; kt++)
            #pragma unroll
            for (int u = 0; u < 4; u++) {
                u32 b0, b1, b2, b3;
                u32 addr = w1_b + (u32)((u * 16 + (lane >> 4) * 8 + (lane & 7)) * 80
                                        + kt * 32 + ((lane >> 3) & 1) * 16);
                ldsm4(b0, b1, b2, b3, addr);
                mma16816(d[2 * u],     a[kt], b0, b1);
                mma16816(d[2 * u + 1], a[kt], b2, b3);
            }

        #pragma unroll
        for (int kk = 0; kk < 4; kk++) {
            a[kk][0] = f22h2(softplus10(d[2*kk][1]),   softplus10(d[2*kk][0]));
            a[kk][1] = f22h2(softplus10(d[2*kk][3]),   softplus10(d[2*kk][2]));
            a[kk][2] = f22h2(softplus10(d[2*kk+1][1]), softplus10(d[2*kk+1][0]));
            a[kk][3] = f22h2(softplus10(d[2*kk+1][3]), softplus10(d[2*kk+1][2]));
        }

        // layers 2 and 3: 64 -> 64
        #pragma unroll 1
        for (int layer = 0; layer < 2; layer++) {
            const u32 wb = (layer == 0) ? w2_b : w3_b;
            #pragma unroll
            for (int nt = 0; nt < 8; nt++)
                #pragma unroll
                for (int v = 0; v < 4; v++) d[nt][v] = 0.f;

            #pragma unroll
            for (int kt = 0; kt < 4; kt++)
                #pragma unroll
                for (int u = 0; u < 4; u++) {
                    u32 b0, b1, b2, b3;
                    u32 addr = wb + (u32)((u * 16 + (lane >> 4) * 8 + (lane & 7)) * 144
                                          + kt * 32 + ((lane >> 3) & 1) * 16);
                    ldsm4(b0, b1, b2, b3, addr);
                    mma16816(d[2 * u],     a[kt], b0, b1);
                    mma16816(d[2 * u + 1], a[kt], b2, b3);
                }

            if (layer == 0) {
                #pragma unroll
                for (int kk = 0; kk < 4; kk++) {
                    a[kk][0] = f22h2(softplus10(d[2*kk][1]),   softplus10(d[2*kk][0]));
                    a[kk][1] = f22h2(softplus10(d[2*kk][3]),   softplus10(d[2*kk][2]));
                    a[kk][2] = f22h2(softplus10(d[2*kk+1][1]), softplus10(d[2*kk+1][0]));
                    a[kk][3] = f22h2(softplus10(d[2*kk+1][3]), softplus10(d[2*kk+1][2]));
                }
            }
        }

        // layer 4: 64 -> 1
        {
            float p0 = 0.f, p1 = 0.f;
            #pragma unroll
            for (int nt = 0; nt < 8; nt++) {
                int c = nt * 8 + 2 * (lane & 3);
                float wv0 = s_w4[c], wv1 = s_w4[c + 1];
                p0 = fmaf(softplus10(d[nt][0]), wv0, p0);
                p0 = fmaf(softplus10(d[nt][1]), wv1, p0);
                p1 = fmaf(softplus10(d[nt][2]), wv0, p1);
                p1 = fmaf(softplus10(d[nt][3]), wv1, p1);
            }
            p0 += __shfl_xor_sync(0xffffffffu, p0, 1);
            p0 += __shfl_xor_sync(0xffffffffu, p0, 2);
            p1 += __shfl_xor_sync(0xffffffffu, p1, 1);
            p1 += __shfl_xor_sync(0xffffffffu, p1, 2);
            if ((lane & 3) == 0) {
                int r0 = blockIdx.x * BLOCK + warp * 32 + mt * 16 + (lane >> 2);
                if (r0 < n) out[r0] = p0;
                int r1 = r0 + 8;
                if (r1 < n) out[r1] = p1;
            }
        }
    }
}

extern "C" void kernel_launch(void* const* d_in, const int* in_sizes, int n_in,
                              void* d_out, int out_size)
{
    const float* x     = (const float*)d_in[0];
    const float* table = (const float*)d_in[1];
    const float* w1    = (const float*)d_in[2];
    const float* w2    = (const float*)d_in[3];
    const float* w3    = (const float*)d_in[4];
    const float* w4    = (const float*)d_in[5];
    float* out = (float*)d_out;

    const int n = in_sizes[0] / 3;

    LvlParams P;
    BuildParams B;
    B.nd = 0; B.total = 0;
    const double pls = exp2(7.0 / 15.0);
    const double l2s = log2(pls);
    for (int l = 0; l < NLV; l++) {
        double s = exp2((double)l * l2s) * 16.0 - 1.0;
        P.scale[l] = (float)s;
        long long r = (long long)ceil(s) + 1;
        P.res[l] = (int)r;
        P.pdoff[l] = 0;
        bool dn = (r * r * r <= (long long)TSZ);
        if (dn && B.nd < 8 && B.total + r * r * r <= PD_CAP) {
            P.pdoff[l] = B.total;
            B.lvl[B.nd] = l;
            B.res[B.nd] = (int)r;
            B.off[B.nd] = B.total;
            B.nd++;
            B.total += (int)(r * r * r);
        }
    }

    if (B.total > 0) {
        int bgrid = (B.total + 255) / 256;
        build_pd<<<bgrid, 256>>>(table, B);
    }

    int grid = (n + BLOCK - 1) / BLOCK;
    sdf_kernel<<<grid, BLOCK>>>(x, table, w1, w2, w3, w4, out, n, P);
}